// round 11
// baseline (speedup 1.0000x reference)
#include <cuda_runtime.h>
#include <cstdint>

#define BATCH 256
#define TSTEPS 1024
#define HID 64
#define DIN 3

// Scratch (device globals — no cudaMalloc allowed).
__device__ float g_h2[BATCH * TSTEPS * HID];

typedef unsigned long long u64;

// ---- packed fp32x2 helpers (ptxas never auto-emits FFMA2) ----
__device__ __forceinline__ u64 fma2(u64 a, u64 b, u64 c) {
    u64 d; asm("fma.rn.f32x2 %0, %1, %2, %3;" : "=l"(d) : "l"(a), "l"(b), "l"(c)); return d;
}
__device__ __forceinline__ u64 packf2(float lo, float hi) {
    u64 d; asm("mov.b64 %0, {%1, %2};" : "=l"(d) : "f"(lo), "f"(hi)); return d;
}
__device__ __forceinline__ float2 unpackf2(u64 v) {
    float2 f; asm("mov.b64 {%0, %1}, %2;" : "=f"(f.x), "=f"(f.y) : "l"(v)); return f;
}
// 16B shared load straight into two 64-bit regs
__device__ __forceinline__ void lds2(u64 &a, u64 &b, uint32_t addr) {
    asm volatile("ld.shared.v2.b64 {%0, %1}, [%2];" : "=l"(a), "=l"(b) : "r"(addr));
}

// ---- single-MUFU activations (tanh.approx) ----
__device__ __forceinline__ float tanha(float x) {
    float r; asm("tanh.approx.f32 %0, %1;" : "=f"(r) : "f"(x)); return r;
}
__device__ __forceinline__ float siga(float x) {
    return fmaf(0.5f, tanha(0.5f * x), 0.5f);
}

// ============================================================================
// Fused 2-layer LSTM — round-10 champion (800us) with ONE change:
// gate exchange buffers transposed to [m*4 + gate] so the cell phase reads
// (i,f,g,o) in a single LDS.128 instead of 4 serial scalar LDS.
// (Gate-side stores become 4-way bank-conflicted STS — fire-and-forget,
// pre-barrier, absorbed under the 1152-cyc fma shadow.)
// One CTA per 2 sequences, 256 threads. Thread j owns gate row j of
// Whh0, Wih1, Whh1 (registers). Pipeline: iter t = l1 step t, l2 step t-1.
// sh1 = h1[t-1], sh2 = h2[t-2]; 2 barriers/step; 256 threads = 256 cells.
// ============================================================================
__global__ void __launch_bounds__(256, 1) lstm_fused(
    const float* __restrict__ x,
    const float* __restrict__ Wih0, const float* __restrict__ Whh0,
    const float* __restrict__ bih0, const float* __restrict__ bhh0,
    const float* __restrict__ Wih1, const float* __restrict__ Whh1,
    const float* __restrict__ bih1, const float* __restrict__ bhh1)
{
    __shared__ __align__(16) float sx[2][TSTEPS * DIN];  // 24 KB
    __shared__ __align__(16) float sh1[2][HID];
    __shared__ __align__(16) float sh2[2][HID];
    __shared__ __align__(16) float sg1[2][256];   // transposed: [seq][m*4+g]
    __shared__ __align__(16) float sg2[2][256];
    const int tid = threadIdx.x;
    const int b0 = blockIdx.x * 2;

    // stage both sequences' inputs
    {
        const float4* xs0 = (const float4*)(x + (size_t)b0 * TSTEPS * DIN);
        const float4* xs1 = (const float4*)(x + (size_t)(b0 + 1) * TSTEPS * DIN);
        #pragma unroll
        for (int i = 0; i < 3; i++) {
            int idx = tid + i * 256;
            ((float4*)sx[0])[idx] = xs0[idx];
            ((float4*)sx[1])[idx] = xs1[idx];
        }
    }

    // per-thread weight rows, packed f32x2 along k
    u64 w0[32], wA[32], wB[32];
    {
        const float4* r0 = (const float4*)(Whh0 + tid * HID);
        const float4* rA = (const float4*)(Wih1 + tid * HID);
        const float4* rB = (const float4*)(Whh1 + tid * HID);
        #pragma unroll
        for (int i = 0; i < 16; i++) {
            float4 v = r0[i]; w0[2*i] = packf2(v.x, v.y); w0[2*i+1] = packf2(v.z, v.w);
            float4 a = rA[i]; wA[2*i] = packf2(a.x, a.y); wA[2*i+1] = packf2(a.z, a.w);
            float4 b = rB[i]; wB[2*i] = packf2(b.x, b.y); wB[2*i+1] = packf2(b.z, b.w);
        }
    }
    const float wx0 = Wih0[tid * 3 + 0], wx1 = Wih0[tid * 3 + 1], wx2 = Wih0[tid * 3 + 2];
    const float bias0 = bih0[tid] + bhh0[tid];
    const float bias1 = bih1[tid] + bhh1[tid];
    const int gtype = tid >> 6;           // gate type (warp-uniform)
    const int gm = tid & 63;              // row within gate
    const int gidx = gm * 4 + gtype;      // transposed store index

    // cell role: tid -> (layer, seq, m)
    const int cl_layer = tid >> 7;
    const int cl_b = (tid >> 6) & 1;
    const int cl_m = tid & 63;
    float c = 0.0f;

    if (tid < 128) ((float*)sh1)[tid] = 0.0f;
    else           ((float*)sh2)[tid - 128] = 0.0f;

    const uint32_t a_h1s0 = (uint32_t)__cvta_generic_to_shared(&sh1[0][0]);
    const uint32_t a_h1s1 = (uint32_t)__cvta_generic_to_shared(&sh1[1][0]);
    const uint32_t a_h2s0 = (uint32_t)__cvta_generic_to_shared(&sh2[0][0]);
    const uint32_t a_h2s1 = (uint32_t)__cvta_generic_to_shared(&sh2[1][0]);
    float* h2out = &g_h2[(size_t)(b0 + cl_b) * TSTEPS * HID + cl_m];
    // cell gate read pointers (float4, 16B-aligned: cl_m*4 floats)
    const float4* cgp = (const float4*)((cl_layer ? &sg2[cl_b][0] : &sg1[cl_b][0]) + cl_m * 4);
    __syncthreads();

    #pragma unroll 1
    for (int t = 0; t <= TSTEPS; t++) {
        // ---- gate phase: 6 dot products, 192 fma2, 64 LDS.128 (all broadcast)
        u64 A0 = 0, A1 = 0, B0 = 0, B1 = 0, C0 = 0, C1 = 0;
        #pragma unroll
        for (int kk = 0; kk < 16; kk++) {
            u64 p0, p1, q0, q1, r0, r1, s0, s1;
            lds2(p0, p1, a_h1s0 + kk * 16);
            lds2(q0, q1, a_h1s1 + kk * 16);
            lds2(r0, r1, a_h2s0 + kk * 16);
            lds2(s0, s1, a_h2s1 + kk * 16);
            A0 = fma2(w0[2*kk],     p0, A0);
            A0 = fma2(w0[2*kk + 1], p1, A0);
            A1 = fma2(w0[2*kk],     q0, A1);
            A1 = fma2(w0[2*kk + 1], q1, A1);
            B0 = fma2(wA[2*kk],     p0, B0);
            B0 = fma2(wA[2*kk + 1], p1, B0);
            B1 = fma2(wA[2*kk],     q0, B1);
            B1 = fma2(wA[2*kk + 1], q1, B1);
            C0 = fma2(wB[2*kk],     r0, C0);
            C0 = fma2(wB[2*kk + 1], r1, C0);
            C1 = fma2(wB[2*kk],     s0, C1);
            C1 = fma2(wB[2*kk + 1], s1, C1);
        }
        const int tx = (t < TSTEPS) ? t : (TSTEPS - 1);
        float xa0 = sx[0][tx*3 + 0], xa1 = sx[0][tx*3 + 1], xa2 = sx[0][tx*3 + 2];
        float xb0 = sx[1][tx*3 + 0], xb1 = sx[1][tx*3 + 1], xb2 = sx[1][tx*3 + 2];
        float2 fA0 = unpackf2(A0), fA1 = unpackf2(A1);
        float2 fB0 = unpackf2(B0), fB1 = unpackf2(B1);
        float2 fC0 = unpackf2(C0), fC1 = unpackf2(C1);
        float pre10 = fA0.x + fA0.y + bias0 + wx0*xa0 + wx1*xa1 + wx2*xa2;
        float pre11 = fA1.x + fA1.y + bias0 + wx0*xb0 + wx1*xb1 + wx2*xb2;
        float pre20 = (fB0.x + fB0.y) + (fC0.x + fC0.y) + bias1;
        float pre21 = (fB1.x + fB1.y) + (fC1.x + fC1.y) + bias1;
        float v10, v11, v20, v21;
        if (gtype == 2) {
            v10 = tanha(pre10); v11 = tanha(pre11);
            v20 = tanha(pre20); v21 = tanha(pre21);
        } else {
            v10 = siga(pre10); v11 = siga(pre11);
            v20 = siga(pre20); v21 = siga(pre21);
        }
        // transposed gate stores (4-way STS conflict, pre-barrier, absorbed)
        sg1[0][gidx] = v10; sg1[1][gidx] = v11;
        sg2[0][gidx] = v20; sg2[1][gidx] = v21;
        __syncthreads();

        // ---- cell phase: one cell per thread; gates via ONE LDS.128 ----
        bool active = cl_layer ? (t >= 1) : (t < TSTEPS);
        if (active) {
            float4 gv = *cgp;   // {i, f, g, o}
            c = fmaf(gv.y, c, gv.x * gv.z);
            float hn = gv.w * tanha(c);
            if (cl_layer) {
                sh2[cl_b][cl_m] = hn;
                h2out[(size_t)(t - 1) * HID] = hn;
            } else {
                sh1[cl_b][cl_m] = hn;
            }
        }
        __syncthreads();
    }
}

// ============================================================================
// Output projection: y[r, 0..2] = W_out · h2[r] + b_out.
// ============================================================================
__global__ void __launch_bounds__(256) proj_kernel(
    const float* __restrict__ Wout, const float* __restrict__ bout,
    float* __restrict__ y)
{
    __shared__ float sw[3 * 64];
    __shared__ float sb[3];
    const int tid = threadIdx.x;
    if (tid < 192) sw[tid] = Wout[tid];
    if (tid < 3)   sb[tid] = bout[tid];
    __syncthreads();

    int gg = blockIdx.x * 256 + tid;
    int r = gg >> 4;
    int seg = gg & 15;
    float4 v = *(const float4*)&g_h2[(size_t)r * HID + seg * 4];
    int s4 = seg * 4;
    float a0 = sw[s4] * v.x + sw[s4+1] * v.y + sw[s4+2] * v.z + sw[s4+3] * v.w;
    float a1 = sw[64+s4] * v.x + sw[64+s4+1] * v.y + sw[64+s4+2] * v.z + sw[64+s4+3] * v.w;
    float a2 = sw[128+s4] * v.x + sw[128+s4+1] * v.y + sw[128+s4+2] * v.z + sw[128+s4+3] * v.w;
    #pragma unroll
    for (int o = 8; o > 0; o >>= 1) {
        a0 += __shfl_xor_sync(0xffffffffu, a0, o);
        a1 += __shfl_xor_sync(0xffffffffu, a1, o);
        a2 += __shfl_xor_sync(0xffffffffu, a2, o);
    }
    if (seg == 0) {
        y[(size_t)r * 3 + 0] = a0 + sb[0];
        y[(size_t)r * 3 + 1] = a1 + sb[1];
        y[(size_t)r * 3 + 2] = a2 + sb[2];
    }
}

extern "C" void kernel_launch(void* const* d_in, const int* in_sizes, int n_in,
                              void* d_out, int out_size)
{
    const float* x    = (const float*)d_in[0];
    const float* Wih0 = (const float*)d_in[1];
    const float* Whh0 = (const float*)d_in[2];
    const float* bih0 = (const float*)d_in[3];
    const float* bhh0 = (const float*)d_in[4];
    const float* Wih1 = (const float*)d_in[5];
    const float* Whh1 = (const float*)d_in[6];
    const float* bih1 = (const float*)d_in[7];
    const float* bhh1 = (const float*)d_in[8];
    const float* Wout = (const float*)d_in[9];
    const float* bout = (const float*)d_in[10];
    float* y = (float*)d_out;

    lstm_fused<<<BATCH / 2, 256>>>(x, Wih0, Whh0, bih0, bhh0,
                                   Wih1, Whh1, bih1, bhh1);
    proj_kernel<<<(BATCH * TSTEPS * 16) / 256, 256>>>(Wout, bout, y);
}